// round 15
// baseline (speedup 1.0000x reference)
#include <cuda_runtime.h>
#include <cuda_bf16.h>
#include <cstdint>

// FirstSpikeDetector: out[b][t] = 1 iff spike_train[b][t] is the first nonzero
// in row b, else 0. Input values are exact 0.0f / 1.0f.
//
// R15 = R14 (fused single node, R1-verbatim store pass) with the scan window
// shrunk to 32 elements: one LDG.32 per lane = exactly ONE 128B cache line
// per row -> total read 2MB (was 4MB). Resolution is trivial: the first-spike
// element index IS the first set ballot lane (no sub-index, no shfl).
// P(no spike in window) = 0.9^32 ~ 3.4% -> ~560 of 16384 rows take the
// rescan-from-0 path (128-elem chunks, residual miss ~1e-6/chunk-1); these
// warps run concurrently across SMs, expected tail cost << the read saving.
//
// Validated model: bench ~= total DRAM bytes / ~5.26 TB/s. 128MB writes are
// compulsory (floor ~24.3us); this closes the last read-bytes headroom.
//
// Falsified (do not retry): .cs/.ldcs (R2), store-before-ballot bursts (R2/R3),
// persistent grids (R3), multi-row fused batching (R4), branch-free store
// loop (R5), STG.256 (R6), memset+detector 2-node splits (R7/R11/R12 --
// beaten by fused R14), 2D pitched memset (R8), fork/join overlap with memset
// nodes (R8/R10), split-fill (R13).

static constexpr int T   = 2048;    // time steps per row
static constexpr int TV4 = T / 4;   // float4s per row (512)

__global__ void __launch_bounds__(256)
first_spike_fused(const float* __restrict__ in, float* __restrict__ out, int rows)
{
    const int gtid = blockIdx.x * blockDim.x + threadIdx.x;
    const int warp = gtid >> 5;               // one warp = one row
    const int lane = gtid & 31;
    if (warp >= rows) return;

    const float* __restrict__ row_in = in + (size_t)warp * T;
    const float4* __restrict__ row_in4 = reinterpret_cast<const float4*>(row_in);
    float4* __restrict__ row_out4 =
        reinterpret_cast<float4*>(out) + (size_t)warp * TV4;

    // ---- scan window: elements 0..31, one LDG.32 per lane (1 cache line) ----
    const float v = row_in[lane];
    const unsigned m = __ballot_sync(0xffffffffu, v != 0.0f);

    int first = T;   // warp-uniform first-spike index; T = no spike
    if (m != 0u) {
        first = __ffs(m) - 1;                 // element index == lane index
    } else {
        // Rescan path (P ~ 3.4% per row): scan from 0 in 128-elem chunks.
        #pragma unroll 1
        for (int base = 0; base < T; base += 128) {
            const float4 u = row_in4[(base >> 2) + lane];
            const unsigned q2 = (u.x != 0.0f ? 1u : 0u) | (u.y != 0.0f ? 2u : 0u) |
                                (u.z != 0.0f ? 4u : 0u) | (u.w != 0.0f ? 8u : 0u);
            const unsigned m2 = __ballot_sync(0xffffffffu, q2 != 0u);
            if (m2) {
                const int s2 = __ffs(m2) - 1;
                int sub2 = __ffs(q2) - 1;                 // valid on lane s2
                sub2 = __shfl_sync(0xffffffffu, sub2, s2);
                first = base + (s2 << 2) + sub2;
                break;                                    // warp-uniform exit
            }
        }
    }

    // ---- store pass: R1's exact structure (best-measured SM fill) ----
    const int fq = first >> 2;    // which float4 holds the spike (512 if none)
    const int fr = first & 3;

    #pragma unroll
    for (int i = lane; i < TV4; i += 32) {
        float4 z = make_float4(0.0f, 0.0f, 0.0f, 0.0f);
        if (i == fq) {
            if      (fr == 0) z.x = 1.0f;
            else if (fr == 1) z.y = 1.0f;
            else if (fr == 2) z.z = 1.0f;
            else              z.w = 1.0f;
        }
        row_out4[i] = z;
    }
}

extern "C" void kernel_launch(void* const* d_in, const int* in_sizes, int n_in,
                              void* d_out, int out_size)
{
    const float* in = (const float*)d_in[0];
    float* out = (float*)d_out;

    const int rows = in_sizes[0] / T;                       // 16384
    const int threads = 256;                                // 8 warps/block
    const int blocks = (rows * 32 + threads - 1) / threads; // 2048

    first_spike_fused<<<blocks, threads>>>(in, out, rows);
}

// round 16
// speedup vs baseline: 1.0731x; 1.0731x over previous
#include <cuda_runtime.h>
#include <cuda_bf16.h>
#include <cstdint>

// FirstSpikeDetector: out[b][t] = 1 iff spike_train[b][t] is the first nonzero
// in row b, else 0. Input values are exact 0.0f / 1.0f.
//
// R16 = R14 verbatim (confirmation re-bench of the best kernel: 25.1us).
//
// Final converged design after 15 rounds:
//   - fused single node (beats memset+detector 2-node splits by ~2us);
//   - one warp per row, scan window = 64 elements (one LDG.64/lane, 4MB total
//     read). Window bracketing: 128 -> 27.3us, 64 -> 25.1us, 32 -> 27.2us
//     (32's 3.4% miss rate puts ~560 warps through a second dependent load
//     chain before their store stream -- costs more than the bytes saved);
//   - R1's store structure verbatim: 16x STG.128/lane with compare-in-loop
//     one-hot injection (every alternative store form measured slower);
//   - 2048 blocks x 256 threads.
// Model: bench ~= total DRAM bytes (132MB) / 5.26 TB/s steady-state write
// wall ~= 25.1us; compulsory floor (128MB writes alone) ~24.3us -> 97%.
//
// Falsified (do not retry): .cs/.ldcs (R2), store-before-ballot bursts (R2/R3),
// persistent grids (R3), multi-row fused batching (R4), branch-free store
// loop (R5), STG.256 (R6), memset+detector splits (R7/R11/R12), 2D pitched
// memset (R8), fork/join overlap with memset nodes (R8/R10), split-fill (R13),
// window 32 (R15), window 128 (R1).

static constexpr int T   = 2048;    // time steps per row
static constexpr int TV4 = T / 4;   // float4s per row (512)

__global__ void __launch_bounds__(256)
first_spike_fused(const float* __restrict__ in, float* __restrict__ out, int rows)
{
    const int gtid = blockIdx.x * blockDim.x + threadIdx.x;
    const int warp = gtid >> 5;               // one warp = one row
    const int lane = gtid & 31;
    if (warp >= rows) return;

    const float* __restrict__ row_in = in + (size_t)warp * T;
    const float2* __restrict__ row_in2 = reinterpret_cast<const float2*>(row_in);
    const float4* __restrict__ row_in4 = reinterpret_cast<const float4*>(row_in);
    float4* __restrict__ row_out4 =
        reinterpret_cast<float4*>(out) + (size_t)warp * TV4;

    // ---- scan window: elements 0..63, one LDG.64 per lane ----
    const float2 v = row_in2[lane];
    const unsigned q = (v.x != 0.0f ? 1u : 0u) | (v.y != 0.0f ? 2u : 0u);
    const unsigned m = __ballot_sync(0xffffffffu, q != 0u);

    int first = T;   // warp-uniform first-spike index; T = no spike
    if (m != 0u) {
        const int src = __ffs(m) - 1;
        int sub = __ffs(q) - 1;                       // valid on lane src
        sub = __shfl_sync(0xffffffffu, sub, src);
        first = (src << 1) + sub;
    } else {
        // Rare path (P ~ 1.2e-3 per row, ~20 rows): rescan from 0 in
        // 128-elem chunks.
        #pragma unroll 1
        for (int base = 0; base < T; base += 128) {
            const float4 u = row_in4[(base >> 2) + lane];
            const unsigned q2 = (u.x != 0.0f ? 1u : 0u) | (u.y != 0.0f ? 2u : 0u) |
                                (u.z != 0.0f ? 4u : 0u) | (u.w != 0.0f ? 8u : 0u);
            const unsigned m2 = __ballot_sync(0xffffffffu, q2 != 0u);
            if (m2) {
                const int s2 = __ffs(m2) - 1;
                int sub2 = __ffs(q2) - 1;             // valid on lane s2
                sub2 = __shfl_sync(0xffffffffu, sub2, s2);
                first = base + (s2 << 2) + sub2;
                break;                                // warp-uniform exit
            }
        }
    }

    // ---- store pass: R1's exact structure (best-measured SM fill) ----
    const int fq = first >> 2;    // which float4 holds the spike (512 if none)
    const int fr = first & 3;

    #pragma unroll
    for (int i = lane; i < TV4; i += 32) {
        float4 z = make_float4(0.0f, 0.0f, 0.0f, 0.0f);
        if (i == fq) {
            if      (fr == 0) z.x = 1.0f;
            else if (fr == 1) z.y = 1.0f;
            else if (fr == 2) z.z = 1.0f;
            else              z.w = 1.0f;
        }
        row_out4[i] = z;
    }
}

extern "C" void kernel_launch(void* const* d_in, const int* in_sizes, int n_in,
                              void* d_out, int out_size)
{
    const float* in = (const float*)d_in[0];
    float* out = (float*)d_out;

    const int rows = in_sizes[0] / T;                       // 16384
    const int threads = 256;                                // 8 warps/block
    const int blocks = (rows * 32 + threads - 1) / threads; // 2048

    first_spike_fused<<<blocks, threads>>>(in, out, rows);
}